// round 4
// baseline (speedup 1.0000x reference)
#include <cuda_runtime.h>
#include <cuda_bf16.h>
#include <math.h>
#include <stdint.h>

// ---------------- problem constants ----------------
#define NFEAT   256
#define NHID    128
#define NHEAD   4
#define NHEADL  6
#define NCLASS  40
#define HIDDIM  (NHID*NHEAD)      // 512
#define MAXN    10000
#define MAXE    160000
#define MAXEDGE (MAXE + MAXN)
#define NEG_SLOPE 0.2f

// ---------------- scratch (static device memory) ----------------
__device__ float g_XW [MAXN * HIDDIM];
__device__ float g_X1 [MAXN * HIDDIM];
__device__ float g_X2 [MAXN * HIDDIM];
__device__ float g_SKIP[MAXN * HIDDIM];
__device__ float g_ASRC[MAXN * NHEADL];
__device__ float g_ADST[MAXN * NHEADL];
__device__ __nv_bfloat16 g_AH[MAXN * HIDDIM];
__device__ __nv_bfloat16 g_AL[MAXN * HIDDIM];
__device__ __nv_bfloat16 g_BH[1024 * 256];   // up to [N=1024, K=256] / [512,512]
__device__ __nv_bfloat16 g_BL[1024 * 256];
__device__ int   g_rowptr[MAXN + 1];
__device__ int   g_deg [MAXN];
__device__ int   g_cnt [MAXN];
__device__ int   g_csrsrc[MAXEDGE];
__device__ int   g_is64;

// ---------------- edge dtype detection ----------------
__global__ void detect_i64_kernel(const int* w) {
    if (threadIdx.x == 0) {
        int all0 = 1;
        #pragma unroll
        for (int i = 0; i < 64; i++) if (w[2*i + 1] != 0) all0 = 0;
        g_is64 = all0;
    }
}

__device__ __forceinline__ int edge_at(const void* ei, long long idx) {
    if (g_is64) return (int)((const long long*)ei)[idx];
    return ((const int*)ei)[idx];
}

// ---------------- CSR build ----------------
__global__ void degree_kernel(const void* ei, int E) {
    int e = blockIdx.x * blockDim.x + threadIdx.x;
    if (e < E) atomicAdd(&g_deg[edge_at(ei, (long long)E + e)], 1);
}

__global__ void scan_kernel(int n) {
    const int CH = (n + 1023) >> 10;
    int t = threadIdx.x;
    int local[16];
    int base = t * CH;
    int run = 0;
    #pragma unroll
    for (int j = 0; j < 16; j++) {
        if (j >= CH) break;
        int idx = base + j;
        int v = (idx < n) ? (g_deg[idx] + 1) : 0;
        run += v;
        local[j] = run;
    }
    int lane = t & 31, wid = t >> 5;
    int x = run;
    #pragma unroll
    for (int o = 1; o < 32; o <<= 1) {
        int y = __shfl_up_sync(0xFFFFFFFFu, x, o);
        if (lane >= o) x += y;
    }
    __shared__ int wsum[32];
    if (lane == 31) wsum[wid] = x;
    __syncthreads();
    if (wid == 0) {
        int w = wsum[lane];
        #pragma unroll
        for (int o = 1; o < 32; o <<= 1) {
            int y = __shfl_up_sync(0xFFFFFFFFu, w, o);
            if (lane >= o) w += y;
        }
        wsum[lane] = w;
    }
    __syncthreads();
    int excl = x - run + (wid > 0 ? wsum[wid - 1] : 0);
    if (t == 0) g_rowptr[0] = 0;
    #pragma unroll
    for (int j = 0; j < 16; j++) {
        if (j >= CH) break;
        int idx = base + j;
        if (idx < n) g_rowptr[idx + 1] = excl + local[j];
    }
}

__global__ void scatter_kernel(const void* ei, int E) {
    int e = blockIdx.x * blockDim.x + threadIdx.x;
    if (e < E) {
        int d = edge_at(ei, (long long)E + e);
        int s = edge_at(ei, e);
        int p = g_rowptr[d] + atomicAdd(&g_cnt[d], 1);
        g_csrsrc[p] = s;
    }
}

__global__ void selfloop_kernel(int N) {
    int n = blockIdx.x * blockDim.x + threadIdx.x;
    if (n < N) g_csrsrc[g_rowptr[n + 1] - 1] = n;
}

// ---------------- fp32 -> split bf16 ----------------
__global__ void split_kernel(const float* __restrict__ A,
                             __nv_bfloat16* __restrict__ hi, __nv_bfloat16* __restrict__ lo, int n) {
    int i = blockIdx.x * blockDim.x + threadIdx.x;
    if (i < n) {
        float v = A[i];
        __nv_bfloat16 h = __float2bfloat16(v);
        hi[i] = h;
        lo[i] = __float2bfloat16(v - __bfloat162float(h));
    }
}

// B [K,N] row-major -> BT hi/lo [N,K] with row offset (for packing two weights)
__global__ void splitT_kernel(const float* __restrict__ B,
                              __nv_bfloat16* __restrict__ hiT, __nv_bfloat16* __restrict__ loT,
                              int K, int N, int rowOff) {
    int i = blockIdx.x * blockDim.x + threadIdx.x;
    if (i < K * N) {
        int k = i / N, n = i - k * N;
        float v = B[i];
        __nv_bfloat16 h = __float2bfloat16(v);
        hiT[(size_t)(n + rowOff) * K + k] = h;
        loT[(size_t)(n + rowOff) * K + k] = __float2bfloat16(v - __bfloat162float(h));
    }
}

// ---------------- split-bf16 tensor-core GEMM ----------------
// C[:, 0:split) and C2[:, 0:N-split) = Ah*Bh + Ah*Bl + Al*Bh (+bias)
#define GBM 128
#define GBN 128
#define GBK 32
#define APADB 80
#define ABYTES (GBM*APADB)                 // 10240
#define BBYTES (GBN*APADB)                 // 10240
#define STAGEB (2*ABYTES + 2*BBYTES)       // 40960
#define SMEM_GEMM (2*STAGEB)               // 81920

__device__ __forceinline__ void cp16(uint32_t dst, const void* src, bool pred) {
    int sz = pred ? 16 : 0;
    asm volatile("cp.async.cg.shared.global [%0], [%1], 16, %2;\n"
                 :: "r"(dst), "l"(src), "r"(sz));
}

__device__ __forceinline__ void ldsm4(uint32_t* r, uint32_t addr) {
    asm volatile("ldmatrix.sync.aligned.m8n8.x4.shared.b16 {%0,%1,%2,%3}, [%4];"
                 : "=r"(r[0]), "=r"(r[1]), "=r"(r[2]), "=r"(r[3]) : "r"(addr));
}

__device__ __forceinline__ void mma16816(float* c, const uint32_t* a, const uint32_t* b) {
    asm volatile("mma.sync.aligned.m16n8k16.row.col.f32.bf16.bf16.f32 "
                 "{%0,%1,%2,%3}, {%4,%5,%6,%7}, {%8,%9}, {%0,%1,%2,%3};"
                 : "+f"(c[0]), "+f"(c[1]), "+f"(c[2]), "+f"(c[3])
                 : "r"(a[0]), "r"(a[1]), "r"(a[2]), "r"(a[3]), "r"(b[0]), "r"(b[1]));
}

__global__ void __launch_bounds__(256, 2)
gemm_split_bf16(const __nv_bfloat16* __restrict__ AH, const __nv_bfloat16* __restrict__ AL,
                const __nv_bfloat16* __restrict__ BTH, const __nv_bfloat16* __restrict__ BTL,
                const float* __restrict__ bias,
                float* __restrict__ C, float* __restrict__ C2, int split,
                int M, int K, int N) {
    extern __shared__ char smem[];
    uint32_t sbase = (uint32_t)__cvta_generic_to_shared(smem);
    int tid = threadIdx.x, lane = tid & 31, warp = tid >> 5;
    int bm = blockIdx.y * GBM, bn = blockIdx.x * GBN;
    int m0 = (warp & 3) * 32, n0 = (warp >> 2) * 64;
    int nIter = K / GBK;

    float acc[2][8][4] = {};

    auto stage_load = [&](int it, int s) {
        int k0 = it * GBK;
        uint32_t sb = sbase + s * STAGEB;
        // A: 128 rows x 4 chunks = 512 assignments over 256 threads
        #pragma unroll
        for (int rep = 0; rep < 2; rep++) {
            int idx = tid + rep * 256;
            int r = idx >> 2, ch = idx & 3;
            bool ok = (bm + r) < M;
            int ra = ok ? (bm + r) : (M - 1);
            const __nv_bfloat16* gH = AH + (size_t)ra * K + k0 + ch * 8;
            const __nv_bfloat16* gL = AL + (size_t)ra * K + k0 + ch * 8;
            cp16(sb + r * APADB + ch * 16, gH, ok);
            cp16(sb + ABYTES + r * APADB + ch * 16, gL, ok);
        }
        // B: 128 rows x 4 chunks
        #pragma unroll
        for (int rep = 0; rep < 2; rep++) {
            int idx = tid + rep * 256;
            int r = idx >> 2, ch = idx & 3;
            bool ok = (bn + r) < N;
            int ra = ok ? (bn + r) : (N - 1);
            const __nv_bfloat16* gH = BTH + (size_t)ra * K + k0 + ch * 8;
            const __nv_bfloat16* gL = BTL + (size_t)ra * K + k0 + ch * 8;
            cp16(sb + 2 * ABYTES + r * APADB + ch * 16, gH, ok);
            cp16(sb + 2 * ABYTES + BBYTES + r * APADB + ch * 16, gL, ok);
        }
    };

    int aRow = lane & 15;
    int aKby = (lane >> 4) * 16;
    int bRow = (lane & 7) + ((lane >> 4) << 3);
    int bKby = ((lane >> 3) & 1) * 16;

    stage_load(0, 0);
    asm volatile("cp.async.commit_group;\n");

    for (int it = 0; it < nIter; it++) {
        int s = it & 1;
        asm volatile("cp.async.wait_group 0;\n");
        __syncthreads();
        if (it + 1 < nIter) {
            stage_load(it + 1, s ^ 1);
            asm volatile("cp.async.commit_group;\n");
        }

        uint32_t sb  = sbase + s * STAGEB;
        uint32_t pAH = sb + (m0 + aRow) * APADB + aKby;
        uint32_t pAL = pAH + ABYTES;
        uint32_t pBH = sb + 2 * ABYTES + (n0 + bRow) * APADB + bKby;

        #pragma unroll
        for (int ks = 0; ks < 2; ks++) {
            int kb = ks * 32;
            uint32_t ah[2][4], al[2][4];
            ldsm4(ah[0], pAH + kb);
            ldsm4(ah[1], pAH + 16 * APADB + kb);
            ldsm4(al[0], pAL + kb);
            ldsm4(al[1], pAL + 16 * APADB + kb);
            #pragma unroll
            for (int nh = 0; nh < 2; nh++) {
                uint32_t pB = pBH + nh * 32 * APADB + kb;
                uint32_t bh01[4], bh23[4], bl01[4], bl23[4];
                ldsm4(bh01, pB);
                ldsm4(bh23, pB + 16 * APADB);
                ldsm4(bl01, pB + BBYTES);
                ldsm4(bl23, pB + BBYTES + 16 * APADB);
                const uint32_t* bh[4] = {bh01, bh01 + 2, bh23, bh23 + 2};
                const uint32_t* bl[4] = {bl01, bl01 + 2, bl23, bl23 + 2};
                #pragma unroll
                for (int mt = 0; mt < 2; mt++)
                    #pragma unroll
                    for (int nt = 0; nt < 4; nt++) {
                        float* a = acc[mt][nh * 4 + nt];
                        mma16816(a, ah[mt], bh[nt]);
                        mma16816(a, ah[mt], bl[nt]);
                        mma16816(a, al[mt], bh[nt]);
                    }
            }
        }
        __syncthreads();
    }

    // epilogue (split writing: cols < split -> C [M,split], else -> C2 [M,N-split])
    #pragma unroll
    for (int mt = 0; mt < 2; mt++) {
        #pragma unroll
        for (int nt = 0; nt < 8; nt++) {
            int r = bm + m0 + mt * 16 + (lane >> 2);
            int c = bn + n0 + nt * 8 + (lane & 3) * 2;
            float b0v = (bias && c < N) ? bias[c] : 0.f;
            float b1v = (bias && c + 1 < N) ? bias[c + 1] : 0.f;
            float* dst; int cc; int w;
            if (c < split) { dst = C;  cc = c;         w = split; }
            else           { dst = C2; cc = c - split; w = N - split; }
            if (r < M) {
                if (c < N)     dst[(size_t)r * w + cc]     = acc[mt][nt][0] + b0v;
                if (c + 1 < N) dst[(size_t)r * w + cc + 1] = acc[mt][nt][1] + b1v;
            }
            if (r + 8 < M) {
                if (c < N)     dst[(size_t)(r + 8) * w + cc]     = acc[mt][nt][2] + b0v;
                if (c + 1 < N) dst[(size_t)(r + 8) * w + cc + 1] = acc[mt][nt][3] + b1v;
            }
        }
    }
}

// ---------------- per-node attention logits ----------------
__global__ void ascore_kernel(const float* __restrict__ xw,
                              const float* __restrict__ atts, const float* __restrict__ attd,
                              float* __restrict__ asrc, float* __restrict__ adst,
                              int N, int H, int C) {
    int gw = (blockIdx.x * blockDim.x + threadIdx.x) >> 5;
    if (gw >= N * H) return;
    int lane = threadIdx.x & 31;
    int n = gw / H, h = gw - n * H;
    const float* row = xw + (size_t)n * H * C + h * C;
    float ss = 0.f, sd = 0.f;
    for (int c = lane; c < C; c += 32) {
        float v = row[c];
        ss = fmaf(v, atts[h * C + c], ss);
        sd = fmaf(v, attd[h * C + c], sd);
    }
    #pragma unroll
    for (int o = 16; o; o >>= 1) {
        ss += __shfl_xor_sync(0xFFFFFFFFu, ss, o);
        sd += __shfl_xor_sync(0xFFFFFFFFu, sd, o);
    }
    if (lane == 0) { asrc[n * H + h] = ss; adst[n * H + h] = sd; }
}

__device__ __forceinline__ float lrelu(float x) { return x > 0.f ? x : NEG_SLOPE * x; }
__device__ __forceinline__ float eluf(float x)  { return x > 0.f ? x : expm1f(x); }

// ---------------- GAT aggregation, 4 heads per warp, fused elu + bf16 split out ----------------
__global__ void gat_agg_concat4(const float* __restrict__ xw,
                                const float* __restrict__ asrc, const float* __restrict__ adst,
                                const float* __restrict__ bias, const float* __restrict__ skip,
                                float* __restrict__ out,
                                __nv_bfloat16* __restrict__ oh, __nv_bfloat16* __restrict__ ol,
                                int N) {
    int n = (blockIdx.x * blockDim.x + threadIdx.x) >> 5;
    if (n >= N) return;
    int lane = threadIdx.x & 31;
    int s0 = g_rowptr[n], s1 = g_rowptr[n + 1];
    float4 ad = *(const float4*)(adst + n * 4);

    float4 m = make_float4(-1e30f, -1e30f, -1e30f, -1e30f);
    for (int i = s0 + lane; i < s1; i += 32) {
        int s = g_csrsrc[i];
        float4 as = *(const float4*)(asrc + s * 4);
        m.x = fmaxf(m.x, lrelu(as.x + ad.x));
        m.y = fmaxf(m.y, lrelu(as.y + ad.y));
        m.z = fmaxf(m.z, lrelu(as.z + ad.z));
        m.w = fmaxf(m.w, lrelu(as.w + ad.w));
    }
    #pragma unroll
    for (int o = 16; o; o >>= 1) {
        m.x = fmaxf(m.x, __shfl_xor_sync(0xFFFFFFFFu, m.x, o));
        m.y = fmaxf(m.y, __shfl_xor_sync(0xFFFFFFFFu, m.y, o));
        m.z = fmaxf(m.z, __shfl_xor_sync(0xFFFFFFFFu, m.z, o));
        m.w = fmaxf(m.w, __shfl_xor_sync(0xFFFFFFFFu, m.w, o));
    }

    float4 acc0 = {0,0,0,0}, acc1 = {0,0,0,0}, acc2 = {0,0,0,0}, acc3 = {0,0,0,0};
    float4 den = {0,0,0,0};
    int sNext = (s0 < s1) ? g_csrsrc[s0] : 0;
    float4 asNext = (s0 < s1) ? *(const float4*)(asrc + sNext * 4) : make_float4(0,0,0,0);
    for (int i = s0; i < s1; i++) {
        int s = sNext;
        float4 as = asNext;
        if (i + 1 < s1) {
            sNext = g_csrsrc[i + 1];
            asNext = *(const float4*)(asrc + sNext * 4);
        }
        float w0 = __expf(lrelu(as.x + ad.x) - m.x);
        float w1 = __expf(lrelu(as.y + ad.y) - m.y);
        float w2 = __expf(lrelu(as.z + ad.z) - m.z);
        float w3 = __expf(lrelu(as.w + ad.w) - m.w);
        den.x += w0; den.y += w1; den.z += w2; den.w += w3;
        const float4* row = (const float4*)(xw + (size_t)s * HIDDIM);
        float4 v0 = row[lane];
        float4 v1 = row[32 + lane];
        float4 v2 = row[64 + lane];
        float4 v3 = row[96 + lane];
        acc0.x = fmaf(w0, v0.x, acc0.x); acc0.y = fmaf(w0, v0.y, acc0.y);
        acc0.z = fmaf(w0, v0.z, acc0.z); acc0.w = fmaf(w0, v0.w, acc0.w);
        acc1.x = fmaf(w1, v1.x, acc1.x); acc1.y = fmaf(w1, v1.y, acc1.y);
        acc1.z = fmaf(w1, v1.z, acc1.z); acc1.w = fmaf(w1, v1.w, acc1.w);
        acc2.x = fmaf(w2, v2.x, acc2.x); acc2.y = fmaf(w2, v2.y, acc2.y);
        acc2.z = fmaf(w2, v2.z, acc2.z); acc2.w = fmaf(w2, v2.w, acc2.w);
        acc3.x = fmaf(w3, v3.x, acc3.x); acc3.y = fmaf(w3, v3.y, acc3.y);
        acc3.z = fmaf(w3, v3.z, acc3.z); acc3.w = fmaf(w3, v3.w, acc3.w);
    }
    float invs[4];
    invs[0] = 1.f / (den.x + 1e-16f); invs[1] = 1.f / (den.y + 1e-16f);
    invs[2] = 1.f / (den.z + 1e-16f); invs[3] = 1.f / (den.w + 1e-16f);
    float4 accs[4] = {acc0, acc1, acc2, acc3};
    #pragma unroll
    for (int h = 0; h < 4; h++) {
        int base = n * HIDDIM + h * NHID + lane * 4;
        float4 bv = *(const float4*)(bias + h * NHID + lane * 4);
        float4 sv = *(const float4*)(skip + base);
        float4 o;
        o.x = eluf(accs[h].x * invs[h] + bv.x + sv.x);
        o.y = eluf(accs[h].y * invs[h] + bv.y + sv.y);
        o.z = eluf(accs[h].z * invs[h] + bv.z + sv.z);
        o.w = eluf(accs[h].w * invs[h] + bv.w + sv.w);
        *(float4*)(out + base) = o;
        __nv_bfloat16 hx = __float2bfloat16(o.x), hy = __float2bfloat16(o.y);
        __nv_bfloat16 hz = __float2bfloat16(o.z), hw = __float2bfloat16(o.w);
        __nv_bfloat162* ph = (__nv_bfloat162*)(oh + base);
        __nv_bfloat162* pl = (__nv_bfloat162*)(ol + base);
        ph[0] = __nv_bfloat162(hx, hy);
        ph[1] = __nv_bfloat162(hz, hw);
        pl[0] = __nv_bfloat162(__float2bfloat16(o.x - __bfloat162float(hx)),
                               __float2bfloat16(o.y - __bfloat162float(hy)));
        pl[1] = __nv_bfloat162(__float2bfloat16(o.z - __bfloat162float(hz)),
                               __float2bfloat16(o.w - __bfloat162float(hw)));
    }
}

// ---------------- final layer: warp per node, all 6 heads, no atomics ----------------
__global__ void gat_agg_mean6(const float* __restrict__ xw,
                              const float* __restrict__ asrc, const float* __restrict__ adst,
                              float* __restrict__ out, int N) {
    int n = (blockIdx.x * blockDim.x + threadIdx.x) >> 5;
    if (n >= N) return;
    int lane = threadIdx.x & 31;
    bool act = lane < 30;
    int h = act ? (lane / 5) : 5;
    int p = act ? (lane - h * 5) : 0;
    int s0 = g_rowptr[n], s1 = g_rowptr[n + 1];
    float ad = adst[n * NHEADL + h];

    float m = -1e30f;
    for (int i = s0; i < s1; i++) {
        int s = g_csrsrc[i];
        float a = asrc[s * NHEADL + h];
        m = fmaxf(m, lrelu(a + ad));
    }

    float4 acc0 = {0,0,0,0}, acc1 = {0,0,0,0};
    float den = 0.f;
    for (int i = s0; i < s1; i++) {
        int s = g_csrsrc[i];
        float w = __expf(lrelu(asrc[s * NHEADL + h] + ad) - m);
        den += w;
        if (act) {
            const float4* row = (const float4*)(xw + (size_t)s * (NHEADL * NCLASS)) + h * 10;
            float4 v0 = row[p], v1 = row[p + 5];
            acc0.x = fmaf(w, v0.x, acc0.x); acc0.y = fmaf(w, v0.y, acc0.y);
            acc0.z = fmaf(w, v0.z, acc0.z); acc0.w = fmaf(w, v0.w, acc0.w);
            acc1.x = fmaf(w, v1.x, acc1.x); acc1.y = fmaf(w, v1.y, acc1.y);
            acc1.z = fmaf(w, v1.z, acc1.z); acc1.w = fmaf(w, v1.w, acc1.w);
        }
    }
    float sc = act ? (1.f / (den + 1e-16f)) * (1.f / (float)NHEADL) : 0.f;
    acc0.x *= sc; acc0.y *= sc; acc0.z *= sc; acc0.w *= sc;
    acc1.x *= sc; acc1.y *= sc; acc1.z *= sc; acc1.w *= sc;

    #define SHF4(d, v, src) \
        d.x = __shfl_sync(0xFFFFFFFFu, v.x, src); \
        d.y = __shfl_sync(0xFFFFFFFFu, v.y, src); \
        d.z = __shfl_sync(0xFFFFFFFFu, v.z, src); \
        d.w = __shfl_sync(0xFFFFFFFFu, v.w, src);
    float4 t;
    SHF4(t, acc0, (lane + 15) & 31);
    acc0.x += t.x; acc0.y += t.y; acc0.z += t.z; acc0.w += t.w;
    SHF4(t, acc1, (lane + 15) & 31);
    acc1.x += t.x; acc1.y += t.y; acc1.z += t.z; acc1.w += t.w;
    float4 a5, a10, b5, b10;
    SHF4(a5,  acc0, (lane + 5) & 31);
    SHF4(a10, acc0, (lane + 10) & 31);
    SHF4(b5,  acc1, (lane + 5) & 31);
    SHF4(b10, acc1, (lane + 10) & 31);
    if (lane < 5) {
        float4* o = (float4*)(out + (size_t)n * NCLASS);
        float4 c0 = o[lane];
        float4 c1 = o[lane + 5];
        c0.x += acc0.x + a5.x + a10.x; c0.y += acc0.y + a5.y + a10.y;
        c0.z += acc0.z + a5.z + a10.z; c0.w += acc0.w + a5.w + a10.w;
        c1.x += acc1.x + b5.x + b10.x; c1.y += acc1.y + b5.y + b10.y;
        c1.z += acc1.z + b5.z + b10.z; c1.w += acc1.w + b5.w + b10.w;
        o[lane] = c0;
        o[lane + 5] = c1;
    }
    #undef SHF4
}

// ---------------- launch ----------------
extern "C" void kernel_launch(void* const* d_in, const int* in_sizes, int n_in,
                              void* d_out, int out_size) {
    const float* x        = (const float*)d_in[0];
    const void*  ei       = d_in[1];
    const float* W0       = (const float*)d_in[2];
    const float* a_src0   = (const float*)d_in[3];
    const float* a_dst0   = (const float*)d_in[4];
    const float* b0       = (const float*)d_in[5];
    const float* Wskip_in = (const float*)d_in[6];
    const float* W1       = (const float*)d_in[7];
    const float* a_src1   = (const float*)d_in[8];
    const float* a_dst1   = (const float*)d_in[9];
    const float* b1       = (const float*)d_in[10];
    const float* W2       = (const float*)d_in[11];
    const float* a_src2   = (const float*)d_in[12];
    const float* a_dst2   = (const float*)d_in[13];
    const float* b2       = (const float*)d_in[14];
    const float* Wskip_out= (const float*)d_in[15];
    float* out = (float*)d_out;

    int N = in_sizes[0] / NFEAT;
    int E = in_sizes[1] / 2;

    float *XW, *X1, *X2, *SKIP, *ASRC, *ADST;
    __nv_bfloat16 *AH, *AL, *BH, *BL;
    int *deg, *cnt;
    cudaGetSymbolAddress((void**)&XW,   g_XW);
    cudaGetSymbolAddress((void**)&X1,   g_X1);
    cudaGetSymbolAddress((void**)&X2,   g_X2);
    cudaGetSymbolAddress((void**)&SKIP, g_SKIP);
    cudaGetSymbolAddress((void**)&ASRC, g_ASRC);
    cudaGetSymbolAddress((void**)&ADST, g_ADST);
    cudaGetSymbolAddress((void**)&AH,   g_AH);
    cudaGetSymbolAddress((void**)&AL,   g_AL);
    cudaGetSymbolAddress((void**)&BH,   g_BH);
    cudaGetSymbolAddress((void**)&BL,   g_BL);
    cudaGetSymbolAddress((void**)&deg,  g_deg);
    cudaGetSymbolAddress((void**)&cnt,  g_cnt);

    cudaFuncSetAttribute(gemm_split_bf16, cudaFuncAttributeMaxDynamicSharedMemorySize, SMEM_GEMM);

    cudaMemsetAsync(deg, 0, N * sizeof(int));
    cudaMemsetAsync(cnt, 0, N * sizeof(int));
    detect_i64_kernel<<<1, 32>>>((const int*)ei);

    dim3 blk(256);
    auto ggrid = [](int M, int Ncol) { return dim3((Ncol + GBN - 1) / GBN, (M + GBM - 1) / GBM); };
    auto cdiv  = [](int a, int b) { return (a + b - 1) / b; };

    int gridN   = cdiv(N * 32, 256);
    int gridH4  = cdiv(N * NHEAD * 32, 256);
    int gridH6  = cdiv(N * NHEADL * 32, 256);

    // ---- layer 0: combined GEMM x @ [W0 | Wskip_in] -> XW, SKIP ----
    split_kernel<<<cdiv(N * NFEAT, 256), blk>>>(x, AH, AL, N * NFEAT);
    splitT_kernel<<<cdiv(NFEAT * HIDDIM, 256), blk>>>(W0,       BH, BL, NFEAT, HIDDIM, 0);
    splitT_kernel<<<cdiv(NFEAT * HIDDIM, 256), blk>>>(Wskip_in, BH, BL, NFEAT, HIDDIM, HIDDIM);
    gemm_split_bf16<<<ggrid(N, 2 * HIDDIM), blk, SMEM_GEMM>>>(
        AH, AL, BH, BL, nullptr, XW, SKIP, HIDDIM, N, NFEAT, 2 * HIDDIM);

    // ---- CSR build ----
    degree_kernel<<<cdiv(E, 256), blk>>>(ei, E);
    scan_kernel<<<1, 1024>>>(N);
    scatter_kernel<<<cdiv(E, 256), blk>>>(ei, E);
    selfloop_kernel<<<cdiv(N, 256), blk>>>(N);

    ascore_kernel<<<gridH4, blk>>>(XW, a_src0, a_dst0, ASRC, ADST, N, NHEAD, NHID);
    gat_agg_concat4<<<gridN, blk>>>(XW, ASRC, ADST, b0, SKIP, X1, AH, AL, N);

    // ---- layer 1 (AH/AL hold split of X1) ----
    splitT_kernel<<<cdiv(HIDDIM * HIDDIM, 256), blk>>>(W1, BH, BL, HIDDIM, HIDDIM, 0);
    gemm_split_bf16<<<ggrid(N, HIDDIM), blk, SMEM_GEMM>>>(
        AH, AL, BH, BL, nullptr, XW, nullptr, HIDDIM, N, HIDDIM, HIDDIM);
    ascore_kernel<<<gridH4, blk>>>(XW, a_src1, a_dst1, ASRC, ADST, N, NHEAD, NHID);
    gat_agg_concat4<<<gridN, blk>>>(XW, ASRC, ADST, b1, X1, X2, AH, AL, N);

    // ---- layer 2 (AH/AL hold split of X2) ----
    splitT_kernel<<<cdiv(HIDDIM * NHEADL * NCLASS, 256), blk>>>(W2, BH, BL, HIDDIM, NHEADL * NCLASS, 0);
    gemm_split_bf16<<<ggrid(N, NHEADL * NCLASS), blk, SMEM_GEMM>>>(
        AH, AL, BH, BL, nullptr, XW, nullptr, NHEADL * NCLASS, N, HIDDIM, NHEADL * NCLASS);
    ascore_kernel<<<gridH6, blk>>>(XW, a_src2, a_dst2, ASRC, ADST, N, NHEADL, NCLASS);
    splitT_kernel<<<cdiv(HIDDIM * NCLASS, 256), blk>>>(Wskip_out, BH, BL, HIDDIM, NCLASS, 0);
    gemm_split_bf16<<<ggrid(N, NCLASS), blk, SMEM_GEMM>>>(
        AH, AL, BH, BL, b2, out, nullptr, NCLASS, N, HIDDIM, NCLASS);
    gat_agg_mean6<<<gridN, blk>>>(XW, ASRC, ADST, out, N);
}

// round 6
// speedup vs baseline: 1.0589x; 1.0589x over previous
#include <cuda_runtime.h>
#include <cuda_bf16.h>
#include <math.h>
#include <stdint.h>

// ---------------- problem constants ----------------
#define NFEAT   256
#define NHID    128
#define NHEAD   4
#define NHEADL  6
#define NCLASS  40
#define HIDDIM  (NHID*NHEAD)      // 512
#define MAXN    10000
#define MAXE    160000
#define MAXEDGE (MAXE + MAXN)
#define NEG_SLOPE 0.2f

// ---------------- scratch (static device memory) ----------------
__device__ float g_XW [MAXN * HIDDIM];
__device__ float g_X1 [MAXN * HIDDIM];
__device__ float g_X2 [MAXN * HIDDIM];
__device__ float g_SKIP[MAXN * HIDDIM];
__device__ float g_ASRC[MAXN * NHEADL];
__device__ float g_ADST[MAXN * NHEADL];
__device__ __nv_bfloat16 g_AH[MAXN * HIDDIM];
__device__ __nv_bfloat16 g_AL[MAXN * HIDDIM];
__device__ __nv_bfloat16 g_BH[1024 * 512];   // packed BT [rows, K]
__device__ __nv_bfloat16 g_BL[1024 * 512];
__device__ int   g_rowptr[MAXN + 1];
__device__ int   g_deg [MAXN];
__device__ int   g_cnt [MAXN];
__device__ int   g_csrsrc[MAXEDGE];
__device__ int   g_is64;

// ---------------- edge dtype detection ----------------
__global__ void detect_i64_kernel(const int* w) {
    if (threadIdx.x == 0) {
        int all0 = 1;
        #pragma unroll
        for (int i = 0; i < 64; i++) if (w[2*i + 1] != 0) all0 = 0;
        g_is64 = all0;
    }
}

__device__ __forceinline__ int edge_at(const void* ei, long long idx) {
    if (g_is64) return (int)((const long long*)ei)[idx];
    return ((const int*)ei)[idx];
}

// ---------------- CSR build ----------------
__global__ void degree_kernel(const void* ei, int E) {
    int e = blockIdx.x * blockDim.x + threadIdx.x;
    if (e < E) atomicAdd(&g_deg[edge_at(ei, (long long)E + e)], 1);
}

__global__ void scan_kernel(int n) {
    const int CH = (n + 1023) >> 10;
    int t = threadIdx.x;
    int local[16];
    int base = t * CH;
    int run = 0;
    #pragma unroll
    for (int j = 0; j < 16; j++) {
        if (j >= CH) break;
        int idx = base + j;
        int v = (idx < n) ? (g_deg[idx] + 1) : 0;
        run += v;
        local[j] = run;
    }
    int lane = t & 31, wid = t >> 5;
    int x = run;
    #pragma unroll
    for (int o = 1; o < 32; o <<= 1) {
        int y = __shfl_up_sync(0xFFFFFFFFu, x, o);
        if (lane >= o) x += y;
    }
    __shared__ int wsum[32];
    if (lane == 31) wsum[wid] = x;
    __syncthreads();
    if (wid == 0) {
        int w = wsum[lane];
        #pragma unroll
        for (int o = 1; o < 32; o <<= 1) {
            int y = __shfl_up_sync(0xFFFFFFFFu, w, o);
            if (lane >= o) w += y;
        }
        wsum[lane] = w;
    }
    __syncthreads();
    int excl = x - run + (wid > 0 ? wsum[wid - 1] : 0);
    if (t == 0) g_rowptr[0] = 0;
    #pragma unroll
    for (int j = 0; j < 16; j++) {
        if (j >= CH) break;
        int idx = base + j;
        if (idx < n) g_rowptr[idx + 1] = excl + local[j];
    }
}

__global__ void scatter_kernel(const void* ei, int E) {
    int e = blockIdx.x * blockDim.x + threadIdx.x;
    if (e < E) {
        int d = edge_at(ei, (long long)E + e);
        int s = edge_at(ei, e);
        int p = g_rowptr[d] + atomicAdd(&g_cnt[d], 1);
        g_csrsrc[p] = s;
    }
}

__global__ void selfloop_kernel(int N) {
    int n = blockIdx.x * blockDim.x + threadIdx.x;
    if (n < N) g_csrsrc[g_rowptr[n + 1] - 1] = n;
}

// ---------------- fp32 -> split bf16 ----------------
__global__ void split_kernel(const float* __restrict__ A,
                             __nv_bfloat16* __restrict__ hi, __nv_bfloat16* __restrict__ lo, int n) {
    int i = blockIdx.x * blockDim.x + threadIdx.x;
    if (i < n) {
        float v = A[i];
        __nv_bfloat16 h = __float2bfloat16(v);
        hi[i] = h;
        lo[i] = __float2bfloat16(v - __bfloat162float(h));
    }
}

// B [K,N] row-major -> BT hi/lo [N,K], tiled transpose (coalesced both sides)
__global__ void splitT_tiled(const float* __restrict__ B,
                             __nv_bfloat16* __restrict__ hiT, __nv_bfloat16* __restrict__ loT,
                             int K, int N, int rowOff) {
    __shared__ float t[32][33];
    int kb = blockIdx.y * 32, nb = blockIdx.x * 32;
    int tx = threadIdx.x, ty = threadIdx.y;   // 32 x 8
    #pragma unroll
    for (int j = ty; j < 32; j += 8) {
        int k = kb + j, n = nb + tx;
        t[j][tx] = (k < K && n < N) ? B[(size_t)k * N + n] : 0.f;
    }
    __syncthreads();
    #pragma unroll
    for (int j = ty; j < 32; j += 8) {
        int n = nb + j, k = kb + tx;
        if (n < N && k < K) {
            float v = t[tx][j];
            __nv_bfloat16 h = __float2bfloat16(v);
            hiT[(size_t)(n + rowOff) * K + k] = h;
            loT[(size_t)(n + rowOff) * K + k] = __float2bfloat16(v - __bfloat162float(h));
        }
    }
}

// ---------------- split-bf16 tensor-core GEMM, 3-stage pipeline ----------------
// C[:,0:split) (no bias) / C2[:,0:Ntot-split) (+bias2) = Ah*Bh + Ah*Bl + Al*Bh
#define GBM 128
#define GBN 64
#define GBK 32
#define APADB 80
#define ABYTES (GBM*APADB)                 // 10240
#define BBYTES (GBN*APADB)                 // 5120
#define STAGEB (2*ABYTES + 2*BBYTES)       // 30720
#define NSTAGE 3
#define SMEM_GEMM (NSTAGE*STAGEB)          // 92160

__device__ __forceinline__ void cp16(uint32_t dst, const void* src) {
    asm volatile("cp.async.cg.shared.global [%0], [%1], 16;\n" :: "r"(dst), "l"(src));
}

__device__ __forceinline__ void ldsm4(uint32_t* r, uint32_t addr) {
    asm volatile("ldmatrix.sync.aligned.m8n8.x4.shared.b16 {%0,%1,%2,%3}, [%4];"
                 : "=r"(r[0]), "=r"(r[1]), "=r"(r[2]), "=r"(r[3]) : "r"(addr));
}

__device__ __forceinline__ void mma16816(float* c, const uint32_t* a, const uint32_t* b) {
    asm volatile("mma.sync.aligned.m16n8k16.row.col.f32.bf16.bf16.f32 "
                 "{%0,%1,%2,%3}, {%4,%5,%6,%7}, {%8,%9}, {%0,%1,%2,%3};"
                 : "+f"(c[0]), "+f"(c[1]), "+f"(c[2]), "+f"(c[3])
                 : "r"(a[0]), "r"(a[1]), "r"(a[2]), "r"(a[3]), "r"(b[0]), "r"(b[1]));
}

__global__ void __launch_bounds__(256, 2)
gemm_split_bf16(const __nv_bfloat16* __restrict__ AH, const __nv_bfloat16* __restrict__ AL,
                const __nv_bfloat16* __restrict__ BTH, const __nv_bfloat16* __restrict__ BTL,
                const float* __restrict__ bias2,
                float* __restrict__ C, float* __restrict__ C2, int split,
                int M, int K, int N) {
    extern __shared__ char smem[];
    uint32_t sbase = (uint32_t)__cvta_generic_to_shared(smem);
    int tid = threadIdx.x, lane = tid & 31, warp = tid >> 5;
    int bm = blockIdx.y * GBM, bn = blockIdx.x * GBN;
    int m0 = (warp >> 1) * 32, n0 = (warp & 1) * 32;
    int nIter = K / GBK;

    float acc[2][4][4] = {};

    auto stage_load = [&](int it, int s) {
        int k0 = it * GBK;
        uint32_t sb = sbase + s * STAGEB;
        #pragma unroll
        for (int rep = 0; rep < 2; rep++) {
            int idx = tid + rep * 256;
            int r = idx >> 2, ch = idx & 3;
            int ra = bm + r; if (ra >= M) ra = M - 1;
            size_t off = (size_t)ra * K + k0 + ch * 8;
            cp16(sb + r * APADB + ch * 16, AH + off);
            cp16(sb + ABYTES + r * APADB + ch * 16, AL + off);
        }
        {
            int r = tid >> 2, ch = tid & 3;
            int ra = bn + r; if (ra >= N) ra = N - 1;
            size_t off = (size_t)ra * K + k0 + ch * 8;
            cp16(sb + 2 * ABYTES + r * APADB + ch * 16, BTH + off);
            cp16(sb + 2 * ABYTES + BBYTES + r * APADB + ch * 16, BTL + off);
        }
    };

    int aRow = lane & 15;
    int aKby = (lane >> 4) * 16;
    int bRow = (lane & 7) + ((lane >> 4) << 3);
    int bKby = ((lane >> 3) & 1) * 16;

    stage_load(0, 0);
    asm volatile("cp.async.commit_group;\n");
    if (nIter > 1) stage_load(1, 1);
    asm volatile("cp.async.commit_group;\n");

    for (int it = 0; it < nIter; it++) {
        int s = it % NSTAGE;
        asm volatile("cp.async.wait_group 1;\n");
        __syncthreads();
        if (it + 2 < nIter) stage_load(it + 2, (it + 2) % NSTAGE);
        asm volatile("cp.async.commit_group;\n");

        uint32_t sb  = sbase + s * STAGEB;
        uint32_t pAH = sb + (m0 + aRow) * APADB + aKby;
        uint32_t pAL = pAH + ABYTES;
        uint32_t pBH = sb + 2 * ABYTES + (n0 + bRow) * APADB + bKby;

        #pragma unroll
        for (int ks = 0; ks < 2; ks++) {
            int kb = ks * 32;
            uint32_t ah[2][4], al[2][4];
            ldsm4(ah[0], pAH + kb);
            ldsm4(ah[1], pAH + 16 * APADB + kb);
            ldsm4(al[0], pAL + kb);
            ldsm4(al[1], pAL + 16 * APADB + kb);
            uint32_t bh01[4], bh23[4], bl01[4], bl23[4];
            ldsm4(bh01, pBH + kb);
            ldsm4(bh23, pBH + 16 * APADB + kb);
            ldsm4(bl01, pBH + BBYTES + kb);
            ldsm4(bl23, pBH + BBYTES + 16 * APADB + kb);
            const uint32_t* bh[4] = {bh01, bh01 + 2, bh23, bh23 + 2};
            const uint32_t* bl[4] = {bl01, bl01 + 2, bl23, bl23 + 2};
            // pass-major: each accumulator's dependent MMAs are 8 apart
            #pragma unroll
            for (int mt = 0; mt < 2; mt++)
                #pragma unroll
                for (int nt = 0; nt < 4; nt++) mma16816(acc[mt][nt], ah[mt], bh[nt]);
            #pragma unroll
            for (int mt = 0; mt < 2; mt++)
                #pragma unroll
                for (int nt = 0; nt < 4; nt++) mma16816(acc[mt][nt], ah[mt], bl[nt]);
            #pragma unroll
            for (int mt = 0; mt < 2; mt++)
                #pragma unroll
                for (int nt = 0; nt < 4; nt++) mma16816(acc[mt][nt], al[mt], bh[nt]);
        }
        __syncthreads();
    }

    // epilogue: cols < split -> C (no bias); else -> C2 (+bias2)
    #pragma unroll
    for (int mt = 0; mt < 2; mt++) {
        #pragma unroll
        for (int nt = 0; nt < 4; nt++) {
            int r = bm + m0 + mt * 16 + (lane >> 2);
            int c = bn + n0 + nt * 8 + (lane & 3) * 2;
            #pragma unroll
            for (int half = 0; half < 2; half++) {
                int rr = r + half * 8;
                if (rr >= M) continue;
                #pragma unroll
                for (int j = 0; j < 2; j++) {
                    int cc = c + j;
                    if (cc >= N) continue;
                    float v = acc[mt][nt][half * 2 + j];
                    if (cc < split) {
                        C[(size_t)rr * split + cc] = v;
                    } else {
                        int c2 = cc - split;
                        if (bias2) v += bias2[c2];
                        C2[(size_t)rr * (N - split) + c2] = v;
                    }
                }
            }
        }
    }
}

// ---------------- per-node attention logits ----------------
__global__ void ascore_kernel(const float* __restrict__ xw,
                              const float* __restrict__ atts, const float* __restrict__ attd,
                              float* __restrict__ asrc, float* __restrict__ adst,
                              int N, int H, int C) {
    int gw = (blockIdx.x * blockDim.x + threadIdx.x) >> 5;
    if (gw >= N * H) return;
    int lane = threadIdx.x & 31;
    int n = gw / H, h = gw - n * H;
    const float* row = xw + (size_t)n * H * C + h * C;
    float ss = 0.f, sd = 0.f;
    for (int c = lane; c < C; c += 32) {
        float v = row[c];
        ss = fmaf(v, atts[h * C + c], ss);
        sd = fmaf(v, attd[h * C + c], sd);
    }
    #pragma unroll
    for (int o = 16; o; o >>= 1) {
        ss += __shfl_xor_sync(0xFFFFFFFFu, ss, o);
        sd += __shfl_xor_sync(0xFFFFFFFFu, sd, o);
    }
    if (lane == 0) { asrc[n * H + h] = ss; adst[n * H + h] = sd; }
}

__device__ __forceinline__ float lrelu(float x) { return x > 0.f ? x : NEG_SLOPE * x; }
__device__ __forceinline__ float eluf(float x)  { return x > 0.f ? x : expm1f(x); }

// ---------------- GAT aggregation, 4 heads per warp, fused elu + bf16 split out ----------------
__global__ void gat_agg_concat4(const float* __restrict__ xw,
                                const float* __restrict__ asrc, const float* __restrict__ adst,
                                const float* __restrict__ bias, const float* __restrict__ skip,
                                float* __restrict__ out,
                                __nv_bfloat16* __restrict__ oh, __nv_bfloat16* __restrict__ ol,
                                int N) {
    int n = (blockIdx.x * blockDim.x + threadIdx.x) >> 5;
    if (n >= N) return;
    int lane = threadIdx.x & 31;
    int s0 = g_rowptr[n], s1 = g_rowptr[n + 1];
    float4 ad = *(const float4*)(adst + n * 4);

    float4 m = make_float4(-1e30f, -1e30f, -1e30f, -1e30f);
    for (int i = s0 + lane; i < s1; i += 32) {
        int s = g_csrsrc[i];
        float4 as = *(const float4*)(asrc + s * 4);
        m.x = fmaxf(m.x, lrelu(as.x + ad.x));
        m.y = fmaxf(m.y, lrelu(as.y + ad.y));
        m.z = fmaxf(m.z, lrelu(as.z + ad.z));
        m.w = fmaxf(m.w, lrelu(as.w + ad.w));
    }
    #pragma unroll
    for (int o = 16; o; o >>= 1) {
        m.x = fmaxf(m.x, __shfl_xor_sync(0xFFFFFFFFu, m.x, o));
        m.y = fmaxf(m.y, __shfl_xor_sync(0xFFFFFFFFu, m.y, o));
        m.z = fmaxf(m.z, __shfl_xor_sync(0xFFFFFFFFu, m.z, o));
        m.w = fmaxf(m.w, __shfl_xor_sync(0xFFFFFFFFu, m.w, o));
    }

    float4 acc0 = {0,0,0,0}, acc1 = {0,0,0,0}, acc2 = {0,0,0,0}, acc3 = {0,0,0,0};
    float4 den = {0,0,0,0};
    int sNext = (s0 < s1) ? g_csrsrc[s0] : 0;
    float4 asNext = (s0 < s1) ? *(const float4*)(asrc + sNext * 4) : make_float4(0,0,0,0);
    for (int i = s0; i < s1; i++) {
        int s = sNext;
        float4 as = asNext;
        if (i + 1 < s1) {
            sNext = g_csrsrc[i + 1];
            asNext = *(const float4*)(asrc + sNext * 4);
        }
        float w0 = __expf(lrelu(as.x + ad.x) - m.x);
        float w1 = __expf(lrelu(as.y + ad.y) - m.y);
        float w2 = __expf(lrelu(as.z + ad.z) - m.z);
        float w3 = __expf(lrelu(as.w + ad.w) - m.w);
        den.x += w0; den.y += w1; den.z += w2; den.w += w3;
        const float4* row = (const float4*)(xw + (size_t)s * HIDDIM);
        float4 v0 = row[lane];
        float4 v1 = row[32 + lane];
        float4 v2 = row[64 + lane];
        float4 v3 = row[96 + lane];
        acc0.x = fmaf(w0, v0.x, acc0.x); acc0.y = fmaf(w0, v0.y, acc0.y);
        acc0.z = fmaf(w0, v0.z, acc0.z); acc0.w = fmaf(w0, v0.w, acc0.w);
        acc1.x = fmaf(w1, v1.x, acc1.x); acc1.y = fmaf(w1, v1.y, acc1.y);
        acc1.z = fmaf(w1, v1.z, acc1.z); acc1.w = fmaf(w1, v1.w, acc1.w);
        acc2.x = fmaf(w2, v2.x, acc2.x); acc2.y = fmaf(w2, v2.y, acc2.y);
        acc2.z = fmaf(w2, v2.z, acc2.z); acc2.w = fmaf(w2, v2.w, acc2.w);
        acc3.x = fmaf(w3, v3.x, acc3.x); acc3.y = fmaf(w3, v3.y, acc3.y);
        acc3.z = fmaf(w3, v3.z, acc3.z); acc3.w = fmaf(w3, v3.w, acc3.w);
    }
    float invs[4];
    invs[0] = 1.f / (den.x + 1e-16f); invs[1] = 1.f / (den.y + 1e-16f);
    invs[2] = 1.f / (den.z + 1e-16f); invs[3] = 1.f / (den.w + 1e-16f);
    float4 accs[4] = {acc0, acc1, acc2, acc3};
    #pragma unroll
    for (int h = 0; h < 4; h++) {
        int base = n * HIDDIM + h * NHID + lane * 4;
        float4 bv = *(const float4*)(bias + h * NHID + lane * 4);
        float4 sv = *(const float4*)(skip + base);
        float4 o;
        o.x = eluf(accs[h].x * invs[h] + bv.x + sv.x);
        o.y = eluf(accs[h].y * invs[h] + bv.y + sv.y);
        o.z = eluf(accs[h].z * invs[h] + bv.z + sv.z);
        o.w = eluf(accs[h].w * invs[h] + bv.w + sv.w);
        *(float4*)(out + base) = o;
        __nv_bfloat16 hx = __float2bfloat16(o.x), hy = __float2bfloat16(o.y);
        __nv_bfloat16 hz = __float2bfloat16(o.z), hw = __float2bfloat16(o.w);
        __nv_bfloat162* ph = (__nv_bfloat162*)(oh + base);
        __nv_bfloat162* pl = (__nv_bfloat162*)(ol + base);
        ph[0] = __nv_bfloat162(hx, hy);
        ph[1] = __nv_bfloat162(hz, hw);
        pl[0] = __nv_bfloat162(__float2bfloat16(o.x - __bfloat162float(hx)),
                               __float2bfloat16(o.y - __bfloat162float(hy)));
        pl[1] = __nv_bfloat162(__float2bfloat16(o.z - __bfloat162float(hz)),
                               __float2bfloat16(o.w - __bfloat162float(hw)));
    }
}

// ---------------- final layer: warp per node, all 6 heads, no atomics ----------------
__global__ void gat_agg_mean6(const float* __restrict__ xw,
                              const float* __restrict__ asrc, const float* __restrict__ adst,
                              float* __restrict__ out, int N) {
    int n = (blockIdx.x * blockDim.x + threadIdx.x) >> 5;
    if (n >= N) return;
    int lane = threadIdx.x & 31;
    bool act = lane < 30;
    int h = act ? (lane / 5) : 5;
    int p = act ? (lane - h * 5) : 0;
    int s0 = g_rowptr[n], s1 = g_rowptr[n + 1];
    float ad = adst[n * NHEADL + h];

    float m = -1e30f;
    for (int i = s0; i < s1; i++) {
        int s = g_csrsrc[i];
        float a = asrc[s * NHEADL + h];
        m = fmaxf(m, lrelu(a + ad));
    }

    float4 acc0 = {0,0,0,0}, acc1 = {0,0,0,0};
    float den = 0.f;
    for (int i = s0; i < s1; i++) {
        int s = g_csrsrc[i];
        float w = __expf(lrelu(asrc[s * NHEADL + h] + ad) - m);
        den += w;
        if (act) {
            const float4* row = (const float4*)(xw + (size_t)s * (NHEADL * NCLASS)) + h * 10;
            float4 v0 = row[p], v1 = row[p + 5];
            acc0.x = fmaf(w, v0.x, acc0.x); acc0.y = fmaf(w, v0.y, acc0.y);
            acc0.z = fmaf(w, v0.z, acc0.z); acc0.w = fmaf(w, v0.w, acc0.w);
            acc1.x = fmaf(w, v1.x, acc1.x); acc1.y = fmaf(w, v1.y, acc1.y);
            acc1.z = fmaf(w, v1.z, acc1.z); acc1.w = fmaf(w, v1.w, acc1.w);
        }
    }
    float sc = act ? (1.f / (den + 1e-16f)) * (1.f / (float)NHEADL) : 0.f;
    acc0.x *= sc; acc0.y *= sc; acc0.z *= sc; acc0.w *= sc;
    acc1.x *= sc; acc1.y *= sc; acc1.z *= sc; acc1.w *= sc;

    #define SHF4(d, v, src) \
        d.x = __shfl_sync(0xFFFFFFFFu, v.x, src); \
        d.y = __shfl_sync(0xFFFFFFFFu, v.y, src); \
        d.z = __shfl_sync(0xFFFFFFFFu, v.z, src); \
        d.w = __shfl_sync(0xFFFFFFFFu, v.w, src);
    float4 t;
    SHF4(t, acc0, (lane + 15) & 31);
    acc0.x += t.x; acc0.y += t.y; acc0.z += t.z; acc0.w += t.w;
    SHF4(t, acc1, (lane + 15) & 31);
    acc1.x += t.x; acc1.y += t.y; acc1.z += t.z; acc1.w += t.w;
    float4 a5, a10, b5, b10;
    SHF4(a5,  acc0, (lane + 5) & 31);
    SHF4(a10, acc0, (lane + 10) & 31);
    SHF4(b5,  acc1, (lane + 5) & 31);
    SHF4(b10, acc1, (lane + 10) & 31);
    if (lane < 5) {
        float4* o = (float4*)(out + (size_t)n * NCLASS);
        float4 c0 = o[lane];
        float4 c1 = o[lane + 5];
        c0.x += acc0.x + a5.x + a10.x; c0.y += acc0.y + a5.y + a10.y;
        c0.z += acc0.z + a5.z + a10.z; c0.w += acc0.w + a5.w + a10.w;
        c1.x += acc1.x + b5.x + b10.x; c1.y += acc1.y + b5.y + b10.y;
        c1.z += acc1.z + b5.z + b10.z; c1.w += acc1.w + b5.w + b10.w;
        o[lane] = c0;
        o[lane + 5] = c1;
    }
    #undef SHF4
}

// ---------------- launch ----------------
extern "C" void kernel_launch(void* const* d_in, const int* in_sizes, int n_in,
                              void* d_out, int out_size) {
    const float* x        = (const float*)d_in[0];
    const void*  ei       = d_in[1];
    const float* W0       = (const float*)d_in[2];
    const float* a_src0   = (const float*)d_in[3];
    const float* a_dst0   = (const float*)d_in[4];
    const float* b0       = (const float*)d_in[5];
    const float* Wskip_in = (const float*)d_in[6];
    const float* W1       = (const float*)d_in[7];
    const float* a_src1   = (const float*)d_in[8];
    const float* a_dst1   = (const float*)d_in[9];
    const float* b1       = (const float*)d_in[10];
    const float* W2       = (const float*)d_in[11];
    const float* a_src2   = (const float*)d_in[12];
    const float* a_dst2   = (const float*)d_in[13];
    const float* b2       = (const float*)d_in[14];
    const float* Wskip_out= (const float*)d_in[15];
    float* out = (float*)d_out;

    int N = in_sizes[0] / NFEAT;
    int E = in_sizes[1] / 2;

    float *XW, *X1, *X2, *SKIP, *ASRC, *ADST;
    __nv_bfloat16 *AH, *AL, *BH, *BL;
    int *deg, *cnt;
    cudaGetSymbolAddress((void**)&XW,   g_XW);
    cudaGetSymbolAddress((void**)&X1,   g_X1);
    cudaGetSymbolAddress((void**)&X2,   g_X2);
    cudaGetSymbolAddress((void**)&SKIP, g_SKIP);
    cudaGetSymbolAddress((void**)&ASRC, g_ASRC);
    cudaGetSymbolAddress((void**)&ADST, g_ADST);
    cudaGetSymbolAddress((void**)&AH,   g_AH);
    cudaGetSymbolAddress((void**)&AL,   g_AL);
    cudaGetSymbolAddress((void**)&BH,   g_BH);
    cudaGetSymbolAddress((void**)&BL,   g_BL);
    cudaGetSymbolAddress((void**)&deg,  g_deg);
    cudaGetSymbolAddress((void**)&cnt,  g_cnt);

    cudaFuncSetAttribute(gemm_split_bf16, cudaFuncAttributeMaxDynamicSharedMemorySize, SMEM_GEMM);

    cudaMemsetAsync(deg, 0, N * sizeof(int));
    cudaMemsetAsync(cnt, 0, N * sizeof(int));
    detect_i64_kernel<<<1, 32>>>((const int*)ei);

    dim3 blk(256);
    dim3 tblk(32, 8);
    auto ggrid = [](int M, int Ncol) { return dim3((Ncol + GBN - 1) / GBN, (M + GBM - 1) / GBM); };
    auto tgrid = [](int K, int Ncol) { return dim3((Ncol + 31) / 32, (K + 31) / 32); };
    auto cdiv  = [](int a, int b) { return (a + b - 1) / b; };

    int gridN   = cdiv(N * 32, 256);
    int gridH4  = cdiv(N * NHEAD * 32, 256);
    int gridH6  = cdiv(N * NHEADL * 32, 256);

    // ---- layer 0: fused x @ [W0 | Wskip_in] -> XW, SKIP ----
    split_kernel<<<cdiv(N * NFEAT, 256), blk>>>(x, AH, AL, N * NFEAT);
    splitT_tiled<<<tgrid(NFEAT, HIDDIM), tblk>>>(W0,       BH, BL, NFEAT, HIDDIM, 0);
    splitT_tiled<<<tgrid(NFEAT, HIDDIM), tblk>>>(Wskip_in, BH, BL, NFEAT, HIDDIM, HIDDIM);
    gemm_split_bf16<<<ggrid(N, 2 * HIDDIM), blk, SMEM_GEMM>>>(
        AH, AL, BH, BL, nullptr, XW, SKIP, HIDDIM, N, NFEAT, 2 * HIDDIM);

    // ---- CSR build ----
    degree_kernel<<<cdiv(E, 256), blk>>>(ei, E);
    scan_kernel<<<1, 1024>>>(N);
    scatter_kernel<<<cdiv(E, 256), blk>>>(ei, E);
    selfloop_kernel<<<cdiv(N, 256), blk>>>(N);

    ascore_kernel<<<gridH4, blk>>>(XW, a_src0, a_dst0, ASRC, ADST, N, NHEAD, NHID);
    gat_agg_concat4<<<gridN, blk>>>(XW, ASRC, ADST, b0, SKIP, X1, AH, AL, N);

    // ---- layer 1 (AH/AL hold split of X1) ----
    splitT_tiled<<<tgrid(HIDDIM, HIDDIM), tblk>>>(W1, BH, BL, HIDDIM, HIDDIM, 0);
    gemm_split_bf16<<<ggrid(N, HIDDIM), blk, SMEM_GEMM>>>(
        AH, AL, BH, BL, nullptr, XW, XW, HIDDIM, N, HIDDIM, HIDDIM);
    ascore_kernel<<<gridH4, blk>>>(XW, a_src1, a_dst1, ASRC, ADST, N, NHEAD, NHID);
    gat_agg_concat4<<<gridN, blk>>>(XW, ASRC, ADST, b1, X1, X2, AH, AL, N);

    // ---- layer 2 (AH/AL hold split of X2): fused x2 @ [W2 | Wskip_out] ----
    splitT_tiled<<<tgrid(HIDDIM, NHEADL * NCLASS), tblk>>>(W2, BH, BL, HIDDIM, NHEADL * NCLASS, 0);
    splitT_tiled<<<tgrid(HIDDIM, NCLASS), tblk>>>(Wskip_out, BH, BL, HIDDIM, NCLASS, NHEADL * NCLASS);
    gemm_split_bf16<<<ggrid(N, NHEADL * NCLASS + NCLASS), blk, SMEM_GEMM>>>(
        AH, AL, BH, BL, b2, XW, out, NHEADL * NCLASS, N, HIDDIM, NHEADL * NCLASS + NCLASS);
    ascore_kernel<<<gridH6, blk>>>(XW, a_src2, a_dst2, ASRC, ADST, N, NHEADL, NCLASS);
    gat_agg_mean6<<<gridN, blk>>>(XW, ASRC, ADST, out, N);
}

// round 7
// speedup vs baseline: 1.1690x; 1.1040x over previous
#include <cuda_runtime.h>
#include <cuda_fp16.h>
#include <math.h>
#include <stdint.h>

// ---------------- problem constants ----------------
#define NFEAT   256
#define NHID    128
#define NHEAD   4
#define NHEADL  6
#define NCLASS  40
#define HIDDIM  (NHID*NHEAD)      // 512
#define MAXN    10000
#define MAXE    160000
#define MAXEDGE (MAXE + MAXN)
#define NEG_SLOPE 0.2f

// ---------------- scratch (static device memory) ----------------
__device__ float g_XW [MAXN * HIDDIM];
__device__ float g_X1 [MAXN * HIDDIM];
__device__ float g_X2 [MAXN * HIDDIM];
__device__ float g_SKIP[MAXN * HIDDIM];
__device__ float g_ASRC[MAXN * NHEADL];
__device__ float g_ADST[MAXN * NHEADL];
__device__ __half g_AH[MAXN * HIDDIM];
__device__ __half g_AL[MAXN * HIDDIM];
__device__ __half g_BT[1024 * 512];          // packed BT [rows, K] fp16
__device__ int   g_rowptr[MAXN + 1];
__device__ int   g_deg [MAXN];
__device__ int   g_cnt [MAXN];
__device__ int   g_csrsrc[MAXEDGE];
__device__ int   g_is64;

// ---------------- edge dtype detection ----------------
__global__ void detect_i64_kernel(const int* w) {
    if (threadIdx.x == 0) {
        int all0 = 1;
        #pragma unroll
        for (int i = 0; i < 64; i++) if (w[2*i + 1] != 0) all0 = 0;
        g_is64 = all0;
    }
}

__device__ __forceinline__ int edge_at(const void* ei, long long idx) {
    if (g_is64) return (int)((const long long*)ei)[idx];
    return ((const int*)ei)[idx];
}

// ---------------- CSR build ----------------
__global__ void degree_kernel(const void* ei, int E) {
    int e = blockIdx.x * blockDim.x + threadIdx.x;
    if (e < E) atomicAdd(&g_deg[edge_at(ei, (long long)E + e)], 1);
}

__global__ void scan_kernel(int n) {
    const int CH = (n + 1023) >> 10;
    int t = threadIdx.x;
    int local[16];
    int base = t * CH;
    int run = 0;
    #pragma unroll
    for (int j = 0; j < 16; j++) {
        if (j >= CH) break;
        int idx = base + j;
        int v = (idx < n) ? (g_deg[idx] + 1) : 0;
        run += v;
        local[j] = run;
    }
    int lane = t & 31, wid = t >> 5;
    int x = run;
    #pragma unroll
    for (int o = 1; o < 32; o <<= 1) {
        int y = __shfl_up_sync(0xFFFFFFFFu, x, o);
        if (lane >= o) x += y;
    }
    __shared__ int wsum[32];
    if (lane == 31) wsum[wid] = x;
    __syncthreads();
    if (wid == 0) {
        int w = wsum[lane];
        #pragma unroll
        for (int o = 1; o < 32; o <<= 1) {
            int y = __shfl_up_sync(0xFFFFFFFFu, w, o);
            if (lane >= o) w += y;
        }
        wsum[lane] = w;
    }
    __syncthreads();
    int excl = x - run + (wid > 0 ? wsum[wid - 1] : 0);
    if (t == 0) g_rowptr[0] = 0;
    #pragma unroll
    for (int j = 0; j < 16; j++) {
        if (j >= CH) break;
        int idx = base + j;
        if (idx < n) g_rowptr[idx + 1] = excl + local[j];
    }
}

__global__ void scatter_kernel(const void* ei, int E) {
    int e = blockIdx.x * blockDim.x + threadIdx.x;
    if (e < E) {
        int d = edge_at(ei, (long long)E + e);
        int s = edge_at(ei, e);
        int p = g_rowptr[d] + atomicAdd(&g_cnt[d], 1);
        g_csrsrc[p] = s;
    }
}

__global__ void selfloop_kernel(int N) {
    int n = blockIdx.x * blockDim.x + threadIdx.x;
    if (n < N) g_csrsrc[g_rowptr[n + 1] - 1] = n;
}

// ---------------- fp32 -> split fp16 ----------------
__global__ void split_kernel(const float* __restrict__ A,
                             __half* __restrict__ hi, __half* __restrict__ lo, int n) {
    int i = blockIdx.x * blockDim.x + threadIdx.x;
    if (i < n) {
        float v = A[i];
        __half h = __float2half(v);
        hi[i] = h;
        lo[i] = __float2half(v - __half2float(h));
    }
}

// B [K,N] row-major -> BT [N,K] fp16, tiled transpose
__global__ void splitT_tiled(const float* __restrict__ B,
                             __half* __restrict__ bT, int K, int N, int rowOff) {
    __shared__ float t[32][33];
    int kb = blockIdx.y * 32, nb = blockIdx.x * 32;
    int tx = threadIdx.x, ty = threadIdx.y;   // 32 x 8
    #pragma unroll
    for (int j = ty; j < 32; j += 8) {
        int k = kb + j, n = nb + tx;
        t[j][tx] = (k < K && n < N) ? B[(size_t)k * N + n] : 0.f;
    }
    __syncthreads();
    #pragma unroll
    for (int j = ty; j < 32; j += 8) {
        int n = nb + j, k = kb + tx;
        if (n < N && k < K)
            bT[(size_t)(n + rowOff) * K + k] = __float2half(t[tx][j]);
    }
}

// ---------------- split-fp16 tensor-core GEMM, 3-stage pipeline ----------------
// C[:,0:split) (no bias) / C2[:,0:Ntot-split) (+bias2) = Ah*B + Al*B
#define GBM 128
#define GBN 64
#define GBK 32
#define APADB 80
#define ABYTES (GBM*APADB)                 // 10240
#define BBYTES (GBN*APADB)                 // 5120
#define STAGEB (2*ABYTES + BBYTES)         // 25600
#define NSTAGE 3
#define SMEM_GEMM (NSTAGE*STAGEB)          // 76800

__device__ __forceinline__ void cp16(uint32_t dst, const void* src) {
    asm volatile("cp.async.cg.shared.global [%0], [%1], 16;\n" :: "r"(dst), "l"(src));
}

__device__ __forceinline__ void ldsm4(uint32_t* r, uint32_t addr) {
    asm volatile("ldmatrix.sync.aligned.m8n8.x4.shared.b16 {%0,%1,%2,%3}, [%4];"
                 : "=r"(r[0]), "=r"(r[1]), "=r"(r[2]), "=r"(r[3]) : "r"(addr));
}

__device__ __forceinline__ void mma16816(float* c, const uint32_t* a, const uint32_t* b) {
    asm volatile("mma.sync.aligned.m16n8k16.row.col.f32.f16.f16.f32 "
                 "{%0,%1,%2,%3}, {%4,%5,%6,%7}, {%8,%9}, {%0,%1,%2,%3};"
                 : "+f"(c[0]), "+f"(c[1]), "+f"(c[2]), "+f"(c[3])
                 : "r"(a[0]), "r"(a[1]), "r"(a[2]), "r"(a[3]), "r"(b[0]), "r"(b[1]));
}

__global__ void __launch_bounds__(256, 2)
gemm_split_f16(const __half* __restrict__ AH, const __half* __restrict__ AL,
               const __half* __restrict__ BT,
               const float* __restrict__ bias2,
               float* __restrict__ C, float* __restrict__ C2, int split,
               int M, int K, int N) {
    extern __shared__ char smem[];
    uint32_t sbase = (uint32_t)__cvta_generic_to_shared(smem);
    int tid = threadIdx.x, lane = tid & 31, warp = tid >> 5;
    int bm = blockIdx.y * GBM, bn = blockIdx.x * GBN;
    int m0 = (warp >> 1) * 32, n0 = (warp & 1) * 32;
    int nIter = K / GBK;

    float acc[2][4][4] = {};

    auto stage_load = [&](int it, int s) {
        int k0 = it * GBK;
        uint32_t sb = sbase + s * STAGEB;
        #pragma unroll
        for (int rep = 0; rep < 2; rep++) {
            int idx = tid + rep * 256;
            int r = idx >> 2, ch = idx & 3;
            int ra = bm + r; if (ra >= M) ra = M - 1;
            size_t off = (size_t)ra * K + k0 + ch * 8;
            cp16(sb + r * APADB + ch * 16, AH + off);
            cp16(sb + ABYTES + r * APADB + ch * 16, AL + off);
        }
        {
            int r = tid >> 2, ch = tid & 3;
            int ra = bn + r; if (ra >= N) ra = N - 1;
            size_t off = (size_t)ra * K + k0 + ch * 8;
            cp16(sb + 2 * ABYTES + r * APADB + ch * 16, BT + off);
        }
    };

    int aRow = lane & 15;
    int aKby = (lane >> 4) * 16;
    int bRow = (lane & 7) + ((lane >> 4) << 3);
    int bKby = ((lane >> 3) & 1) * 16;

    stage_load(0, 0);
    asm volatile("cp.async.commit_group;\n");
    if (nIter > 1) stage_load(1, 1);
    asm volatile("cp.async.commit_group;\n");

    for (int it = 0; it < nIter; it++) {
        int s = it % NSTAGE;
        asm volatile("cp.async.wait_group 1;\n");
        __syncthreads();
        if (it + 2 < nIter) stage_load(it + 2, (it + 2) % NSTAGE);
        asm volatile("cp.async.commit_group;\n");

        uint32_t sb  = sbase + s * STAGEB;
        uint32_t pAH = sb + (m0 + aRow) * APADB + aKby;
        uint32_t pAL = pAH + ABYTES;
        uint32_t pB  = sb + 2 * ABYTES + (n0 + bRow) * APADB + bKby;

        #pragma unroll
        for (int ks = 0; ks < 2; ks++) {
            int kb = ks * 32;
            uint32_t ah[2][4], al[2][4];
            ldsm4(ah[0], pAH + kb);
            ldsm4(ah[1], pAH + 16 * APADB + kb);
            ldsm4(al[0], pAL + kb);
            ldsm4(al[1], pAL + 16 * APADB + kb);
            uint32_t b01[4], b23[4];
            ldsm4(b01, pB + kb);
            ldsm4(b23, pB + 16 * APADB + kb);
            const uint32_t* bf[4] = {b01, b01 + 2, b23, b23 + 2};
            // pass-major: each accumulator's dependent MMAs are 8 apart
            #pragma unroll
            for (int mt = 0; mt < 2; mt++)
                #pragma unroll
                for (int nt = 0; nt < 4; nt++) mma16816(acc[mt][nt], ah[mt], bf[nt]);
            #pragma unroll
            for (int mt = 0; mt < 2; mt++)
                #pragma unroll
                for (int nt = 0; nt < 4; nt++) mma16816(acc[mt][nt], al[mt], bf[nt]);
        }
        __syncthreads();
    }

    // epilogue: cols < split -> C (no bias); else -> C2 (+bias2)
    #pragma unroll
    for (int mt = 0; mt < 2; mt++) {
        #pragma unroll
        for (int nt = 0; nt < 4; nt++) {
            int r = bm + m0 + mt * 16 + (lane >> 2);
            int c = bn + n0 + nt * 8 + (lane & 3) * 2;
            #pragma unroll
            for (int half = 0; half < 2; half++) {
                int rr = r + half * 8;
                if (rr >= M) continue;
                #pragma unroll
                for (int j = 0; j < 2; j++) {
                    int cc = c + j;
                    if (cc >= N) continue;
                    float v = acc[mt][nt][half * 2 + j];
                    if (cc < split) {
                        C[(size_t)rr * split + cc] = v;
                    } else {
                        int c2 = cc - split;
                        if (bias2) v += bias2[c2];
                        C2[(size_t)rr * (N - split) + c2] = v;
                    }
                }
            }
        }
    }
}

// ---------------- per-node attention logits ----------------
__global__ void ascore_kernel(const float* __restrict__ xw,
                              const float* __restrict__ atts, const float* __restrict__ attd,
                              float* __restrict__ asrc, float* __restrict__ adst,
                              int N, int H, int C) {
    int gw = (blockIdx.x * blockDim.x + threadIdx.x) >> 5;
    if (gw >= N * H) return;
    int lane = threadIdx.x & 31;
    int n = gw / H, h = gw - n * H;
    const float* row = xw + (size_t)n * H * C + h * C;
    float ss = 0.f, sd = 0.f;
    for (int c = lane; c < C; c += 32) {
        float v = row[c];
        ss = fmaf(v, atts[h * C + c], ss);
        sd = fmaf(v, attd[h * C + c], sd);
    }
    #pragma unroll
    for (int o = 16; o; o >>= 1) {
        ss += __shfl_xor_sync(0xFFFFFFFFu, ss, o);
        sd += __shfl_xor_sync(0xFFFFFFFFu, sd, o);
    }
    if (lane == 0) { asrc[n * H + h] = ss; adst[n * H + h] = sd; }
}

__device__ __forceinline__ float lrelu(float x) { return x > 0.f ? x : NEG_SLOPE * x; }
__device__ __forceinline__ float eluf(float x)  { return x > 0.f ? x : expm1f(x); }

// ---------------- GAT aggregation, 4 heads per warp, fused elu + fp16 split out ----------------
__global__ void gat_agg_concat4(const float* __restrict__ xw,
                                const float* __restrict__ asrc, const float* __restrict__ adst,
                                const float* __restrict__ bias, const float* __restrict__ skip,
                                float* __restrict__ out,
                                __half* __restrict__ oh, __half* __restrict__ ol,
                                int N) {
    int n = (blockIdx.x * blockDim.x + threadIdx.x) >> 5;
    if (n >= N) return;
    int lane = threadIdx.x & 31;
    int s0 = g_rowptr[n], s1 = g_rowptr[n + 1];
    float4 ad = *(const float4*)(adst + n * 4);

    float4 m = make_float4(-1e30f, -1e30f, -1e30f, -1e30f);
    for (int i = s0 + lane; i < s1; i += 32) {
        int s = g_csrsrc[i];
        float4 as = *(const float4*)(asrc + s * 4);
        m.x = fmaxf(m.x, lrelu(as.x + ad.x));
        m.y = fmaxf(m.y, lrelu(as.y + ad.y));
        m.z = fmaxf(m.z, lrelu(as.z + ad.z));
        m.w = fmaxf(m.w, lrelu(as.w + ad.w));
    }
    #pragma unroll
    for (int o = 16; o; o >>= 1) {
        m.x = fmaxf(m.x, __shfl_xor_sync(0xFFFFFFFFu, m.x, o));
        m.y = fmaxf(m.y, __shfl_xor_sync(0xFFFFFFFFu, m.y, o));
        m.z = fmaxf(m.z, __shfl_xor_sync(0xFFFFFFFFu, m.z, o));
        m.w = fmaxf(m.w, __shfl_xor_sync(0xFFFFFFFFu, m.w, o));
    }

    float4 acc0 = {0,0,0,0}, acc1 = {0,0,0,0}, acc2 = {0,0,0,0}, acc3 = {0,0,0,0};
    float4 den = {0,0,0,0};
    int sNext = (s0 < s1) ? g_csrsrc[s0] : 0;
    float4 asNext = (s0 < s1) ? *(const float4*)(asrc + sNext * 4) : make_float4(0,0,0,0);
    for (int i = s0; i < s1; i++) {
        int s = sNext;
        float4 as = asNext;
        if (i + 1 < s1) {
            sNext = g_csrsrc[i + 1];
            asNext = *(const float4*)(asrc + sNext * 4);
        }
        float w0 = __expf(lrelu(as.x + ad.x) - m.x);
        float w1 = __expf(lrelu(as.y + ad.y) - m.y);
        float w2 = __expf(lrelu(as.z + ad.z) - m.z);
        float w3 = __expf(lrelu(as.w + ad.w) - m.w);
        den.x += w0; den.y += w1; den.z += w2; den.w += w3;
        const float4* row = (const float4*)(xw + (size_t)s * HIDDIM);
        float4 v0 = row[lane];
        float4 v1 = row[32 + lane];
        float4 v2 = row[64 + lane];
        float4 v3 = row[96 + lane];
        acc0.x = fmaf(w0, v0.x, acc0.x); acc0.y = fmaf(w0, v0.y, acc0.y);
        acc0.z = fmaf(w0, v0.z, acc0.z); acc0.w = fmaf(w0, v0.w, acc0.w);
        acc1.x = fmaf(w1, v1.x, acc1.x); acc1.y = fmaf(w1, v1.y, acc1.y);
        acc1.z = fmaf(w1, v1.z, acc1.z); acc1.w = fmaf(w1, v1.w, acc1.w);
        acc2.x = fmaf(w2, v2.x, acc2.x); acc2.y = fmaf(w2, v2.y, acc2.y);
        acc2.z = fmaf(w2, v2.z, acc2.z); acc2.w = fmaf(w2, v2.w, acc2.w);
        acc3.x = fmaf(w3, v3.x, acc3.x); acc3.y = fmaf(w3, v3.y, acc3.y);
        acc3.z = fmaf(w3, v3.z, acc3.z); acc3.w = fmaf(w3, v3.w, acc3.w);
    }
    float invs[4];
    invs[0] = 1.f / (den.x + 1e-16f); invs[1] = 1.f / (den.y + 1e-16f);
    invs[2] = 1.f / (den.z + 1e-16f); invs[3] = 1.f / (den.w + 1e-16f);
    float4 accs[4] = {acc0, acc1, acc2, acc3};
    #pragma unroll
    for (int h = 0; h < 4; h++) {
        int base = n * HIDDIM + h * NHID + lane * 4;
        float4 bv = *(const float4*)(bias + h * NHID + lane * 4);
        float4 sv = *(const float4*)(skip + base);
        float4 o;
        o.x = eluf(accs[h].x * invs[h] + bv.x + sv.x);
        o.y = eluf(accs[h].y * invs[h] + bv.y + sv.y);
        o.z = eluf(accs[h].z * invs[h] + bv.z + sv.z);
        o.w = eluf(accs[h].w * invs[h] + bv.w + sv.w);
        *(float4*)(out + base) = o;
        __half hx = __float2half(o.x), hy = __float2half(o.y);
        __half hz = __float2half(o.z), hw = __float2half(o.w);
        __half2* ph = (__half2*)(oh + base);
        __half2* pl = (__half2*)(ol + base);
        ph[0] = __halves2half2(hx, hy);
        ph[1] = __halves2half2(hz, hw);
        pl[0] = __halves2half2(__float2half(o.x - __half2float(hx)),
                               __float2half(o.y - __half2float(hy)));
        pl[1] = __halves2half2(__float2half(o.z - __half2float(hz)),
                               __float2half(o.w - __half2float(hw)));
    }
}

// ---------------- final layer: warp per node, all 6 heads, no atomics ----------------
__global__ void gat_agg_mean6(const float* __restrict__ xw,
                              const float* __restrict__ asrc, const float* __restrict__ adst,
                              float* __restrict__ out, int N) {
    int n = (blockIdx.x * blockDim.x + threadIdx.x) >> 5;
    if (n >= N) return;
    int lane = threadIdx.x & 31;
    bool act = lane < 30;
    int h = act ? (lane / 5) : 5;
    int p = act ? (lane - h * 5) : 0;
    int s0 = g_rowptr[n], s1 = g_rowptr[n + 1];
    float ad = adst[n * NHEADL + h];

    float m = -1e30f;
    for (int i = s0; i < s1; i++) {
        int s = g_csrsrc[i];
        float a = asrc[s * NHEADL + h];
        m = fmaxf(m, lrelu(a + ad));
    }

    float4 acc0 = {0,0,0,0}, acc1 = {0,0,0,0};
    float den = 0.f;
    for (int i = s0; i < s1; i++) {
        int s = g_csrsrc[i];
        float w = __expf(lrelu(asrc[s * NHEADL + h] + ad) - m);
        den += w;
        if (act) {
            const float4* row = (const float4*)(xw + (size_t)s * (NHEADL * NCLASS)) + h * 10;
            float4 v0 = row[p], v1 = row[p + 5];
            acc0.x = fmaf(w, v0.x, acc0.x); acc0.y = fmaf(w, v0.y, acc0.y);
            acc0.z = fmaf(w, v0.z, acc0.z); acc0.w = fmaf(w, v0.w, acc0.w);
            acc1.x = fmaf(w, v1.x, acc1.x); acc1.y = fmaf(w, v1.y, acc1.y);
            acc1.z = fmaf(w, v1.z, acc1.z); acc1.w = fmaf(w, v1.w, acc1.w);
        }
    }
    float sc = act ? (1.f / (den + 1e-16f)) * (1.f / (float)NHEADL) : 0.f;
    acc0.x *= sc; acc0.y *= sc; acc0.z *= sc; acc0.w *= sc;
    acc1.x *= sc; acc1.y *= sc; acc1.z *= sc; acc1.w *= sc;

    #define SHF4(d, v, src) \
        d.x = __shfl_sync(0xFFFFFFFFu, v.x, src); \
        d.y = __shfl_sync(0xFFFFFFFFu, v.y, src); \
        d.z = __shfl_sync(0xFFFFFFFFu, v.z, src); \
        d.w = __shfl_sync(0xFFFFFFFFu, v.w, src);
    float4 t;
    SHF4(t, acc0, (lane + 15) & 31);
    acc0.x += t.x; acc0.y += t.y; acc0.z += t.z; acc0.w += t.w;
    SHF4(t, acc1, (lane + 15) & 31);
    acc1.x += t.x; acc1.y += t.y; acc1.z += t.z; acc1.w += t.w;
    float4 a5, a10, b5, b10;
    SHF4(a5,  acc0, (lane + 5) & 31);
    SHF4(a10, acc0, (lane + 10) & 31);
    SHF4(b5,  acc1, (lane + 5) & 31);
    SHF4(b10, acc1, (lane + 10) & 31);
    if (lane < 5) {
        float4* o = (float4*)(out + (size_t)n * NCLASS);
        float4 c0 = o[lane];
        float4 c1 = o[lane + 5];
        c0.x += acc0.x + a5.x + a10.x; c0.y += acc0.y + a5.y + a10.y;
        c0.z += acc0.z + a5.z + a10.z; c0.w += acc0.w + a5.w + a10.w;
        c1.x += acc1.x + b5.x + b10.x; c1.y += acc1.y + b5.y + b10.y;
        c1.z += acc1.z + b5.z + b10.z; c1.w += acc1.w + b5.w + b10.w;
        o[lane] = c0;
        o[lane + 5] = c1;
    }
    #undef SHF4
}

// ---------------- launch ----------------
extern "C" void kernel_launch(void* const* d_in, const int* in_sizes, int n_in,
                              void* d_out, int out_size) {
    const float* x        = (const float*)d_in[0];
    const void*  ei       = d_in[1];
    const float* W0       = (const float*)d_in[2];
    const float* a_src0   = (const float*)d_in[3];
    const float* a_dst0   = (const float*)d_in[4];
    const float* b0       = (const float*)d_in[5];
    const float* Wskip_in = (const float*)d_in[6];
    const float* W1       = (const float*)d_in[7];
    const float* a_src1   = (const float*)d_in[8];
    const float* a_dst1   = (const float*)d_in[9];
    const float* b1       = (const float*)d_in[10];
    const float* W2       = (const float*)d_in[11];
    const float* a_src2   = (const float*)d_in[12];
    const float* a_dst2   = (const float*)d_in[13];
    const float* b2       = (const float*)d_in[14];
    const float* Wskip_out= (const float*)d_in[15];
    float* out = (float*)d_out;

    int N = in_sizes[0] / NFEAT;
    int E = in_sizes[1] / 2;

    float *XW, *X1, *X2, *SKIP, *ASRC, *ADST;
    __half *AH, *AL, *BT;
    int *deg, *cnt;
    cudaGetSymbolAddress((void**)&XW,   g_XW);
    cudaGetSymbolAddress((void**)&X1,   g_X1);
    cudaGetSymbolAddress((void**)&X2,   g_X2);
    cudaGetSymbolAddress((void**)&SKIP, g_SKIP);
    cudaGetSymbolAddress((void**)&ASRC, g_ASRC);
    cudaGetSymbolAddress((void**)&ADST, g_ADST);
    cudaGetSymbolAddress((void**)&AH,   g_AH);
    cudaGetSymbolAddress((void**)&AL,   g_AL);
    cudaGetSymbolAddress((void**)&BT,   g_BT);
    cudaGetSymbolAddress((void**)&deg,  g_deg);
    cudaGetSymbolAddress((void**)&cnt,  g_cnt);

    cudaFuncSetAttribute(gemm_split_f16, cudaFuncAttributeMaxDynamicSharedMemorySize, SMEM_GEMM);

    cudaMemsetAsync(deg, 0, N * sizeof(int));
    cudaMemsetAsync(cnt, 0, N * sizeof(int));
    detect_i64_kernel<<<1, 32>>>((const int*)ei);

    dim3 blk(256);
    dim3 tblk(32, 8);
    auto ggrid = [](int M, int Ncol) { return dim3((Ncol + GBN - 1) / GBN, (M + GBM - 1) / GBM); };
    auto tgrid = [](int K, int Ncol) { return dim3((Ncol + 31) / 32, (K + 31) / 32); };
    auto cdiv  = [](int a, int b) { return (a + b - 1) / b; };

    int gridN   = cdiv(N * 32, 256);
    int gridH4  = cdiv(N * NHEAD * 32, 256);
    int gridH6  = cdiv(N * NHEADL * 32, 256);

    // ---- layer 0: fused x @ [W0 | Wskip_in] -> XW, SKIP ----
    split_kernel<<<cdiv(N * NFEAT, 256), blk>>>(x, AH, AL, N * NFEAT);
    splitT_tiled<<<tgrid(NFEAT, HIDDIM), tblk>>>(W0,       BT, NFEAT, HIDDIM, 0);
    splitT_tiled<<<tgrid(NFEAT, HIDDIM), tblk>>>(Wskip_in, BT, NFEAT, HIDDIM, HIDDIM);
    gemm_split_f16<<<ggrid(N, 2 * HIDDIM), blk, SMEM_GEMM>>>(
        AH, AL, BT, nullptr, XW, SKIP, HIDDIM, N, NFEAT, 2 * HIDDIM);

    // ---- CSR build ----
    degree_kernel<<<cdiv(E, 256), blk>>>(ei, E);
    scan_kernel<<<1, 1024>>>(N);
    scatter_kernel<<<cdiv(E, 256), blk>>>(ei, E);
    selfloop_kernel<<<cdiv(N, 256), blk>>>(N);

    ascore_kernel<<<gridH4, blk>>>(XW, a_src0, a_dst0, ASRC, ADST, N, NHEAD, NHID);
    gat_agg_concat4<<<gridN, blk>>>(XW, ASRC, ADST, b0, SKIP, X1, AH, AL, N);

    // ---- layer 1 (AH/AL hold split of X1) ----
    splitT_tiled<<<tgrid(HIDDIM, HIDDIM), tblk>>>(W1, BT, HIDDIM, HIDDIM, 0);
    gemm_split_f16<<<ggrid(N, HIDDIM), blk, SMEM_GEMM>>>(
        AH, AL, BT, nullptr, XW, XW, HIDDIM, N, HIDDIM, HIDDIM);
    ascore_kernel<<<gridH4, blk>>>(XW, a_src1, a_dst1, ASRC, ADST, N, NHEAD, NHID);
    gat_agg_concat4<<<gridN, blk>>>(XW, ASRC, ADST, b1, X1, X2, AH, AL, N);

    // ---- layer 2 (AH/AL hold split of X2): fused x2 @ [W2 | Wskip_out] ----
    splitT_tiled<<<tgrid(HIDDIM, NHEADL * NCLASS), tblk>>>(W2, BT, HIDDIM, NHEADL * NCLASS, 0);
    splitT_tiled<<<tgrid(HIDDIM, NCLASS), tblk>>>(Wskip_out, BT, HIDDIM, NCLASS, NHEADL * NCLASS);
    gemm_split_f16<<<ggrid(N, NHEADL * NCLASS + NCLASS), blk, SMEM_GEMM>>>(
        AH, AL, BT, b2, XW, out, NHEADL * NCLASS, N, HIDDIM, NHEADL * NCLASS + NCLASS);
    ascore_kernel<<<gridH6, blk>>>(XW, a_src2, a_dst2, ASRC, ADST, N, NHEADL, NCLASS);
    gat_agg_mean6<<<gridN, blk>>>(XW, ASRC, ADST, out, N);
}